// round 14
// baseline (speedup 1.0000x reference)
#include <cuda_runtime.h>
#include <cstdint>

#define NN 50000
#define NE 800000

// ================= scratch =================
__device__ __align__(16) float g_agg[NN * 96];
__device__ __align__(16) float g_h1 [NN * 96];
__device__ __align__(16) float g_h2 [NN * 64];
__device__ __align__(16) float g_h3 [NN * 96];
__device__ __align__(16) float g_h4 [NN * 96];
__device__ __align__(16) float g_h5 [NN * 16];
__device__ __align__(16) float g_stats[5][192];   // [layer][sum(96) | sq(96)]
__device__ __align__(16) float g_sc [5][96];
__device__ __align__(16) float g_sh [5][96];
__device__ int g_ctr[2];                          // work-stealing counters
// CSR scratch (src index + edge attr packed)
__device__ int   g_deg      [NN];
__device__ int   g_row_start[NN];
__device__ int   g_pos      [NN];
__device__ __align__(8) int2 g_csr[NE];           // {src, float_as_int(ea)}

// ================= CSR build =================
__global__ void hist_kernel(const int* __restrict__ dst, int* __restrict__ deg)
{
    int i = blockIdx.x * blockDim.x + threadIdx.x;
    if (i < NE) atomicAdd(&deg[dst[i]], 1);
}

// scan also zeroes the BN stats buffers and work counters
__global__ void scan_kernel(const int* __restrict__ deg,
                            int* __restrict__ row_start,
                            int* __restrict__ pos,
                            float* __restrict__ stats,
                            int* __restrict__ ctr)
{
    constexpr int T = 1024;
    constexpr int CH = (NN + T - 1) / T;
    __shared__ int warp_sums[32];
    int t = threadIdx.x;
    int base = t * CH;

    if (t < 5 * 192 / 2) reinterpret_cast<float2*>(stats)[t] = make_float2(0.f, 0.f);
    if (t < 2) ctr[t] = 0;

    int s = 0;
    for (int i = 0; i < CH; i++) {
        int idx = base + i;
        if (idx < NN) s += deg[idx];
    }
    int lane = t & 31, wid = t >> 5;
    int v = s;
#pragma unroll
    for (int o = 1; o < 32; o <<= 1) {
        int u = __shfl_up_sync(0xffffffff, v, o);
        if (lane >= o) v += u;
    }
    if (lane == 31) warp_sums[wid] = v;
    __syncthreads();
    if (wid == 0) {
        int w = warp_sums[lane];
#pragma unroll
        for (int o = 1; o < 32; o <<= 1) {
            int u = __shfl_up_sync(0xffffffff, w, o);
            if (lane >= o) w += u;
        }
        warp_sums[lane] = w;
    }
    __syncthreads();
    int excl = v - s + (wid > 0 ? warp_sums[wid - 1] : 0);

    int running = excl;
    for (int i = 0; i < CH; i++) {
        int idx = base + i;
        if (idx < NN) {
            row_start[idx] = running;
            pos[idx]       = running;
            running += deg[idx];
        }
    }
}

__global__ void scatter_kernel(const int* __restrict__ src,
                               const int* __restrict__ dst,
                               const float* __restrict__ ea,
                               int* __restrict__ pos,
                               int2* __restrict__ csr)
{
    int i = blockIdx.x * blockDim.x + threadIdx.x;
    if (i >= NE) return;
    int slot = atomicAdd(&pos[dst[i]], 1);
    csr[slot] = make_int2(src[i], __float_as_int(ea[i]));
}

// ================= work-stealing CSR gather aggregation =================
// Persistent grid; each warp pulls node IDs from a global counter.
__global__ void __launch_bounds__(256)
aggregate_kernel(const float* __restrict__ xin,
                 const float* __restrict__ sc,
                 const float* __restrict__ sh,
                 const float* __restrict__ lw,
                 const float* __restrict__ lb,
                 const int* __restrict__ row_start,
                 const int* __restrict__ deg,
                 const int2* __restrict__ csr,
                 int* __restrict__ ctr,
                 float* __restrict__ agg)
{
    int lane = threadIdx.x & 31;

    float lw0 = lw[lane], lw1 = lw[lane + 32], lw2 = lw[lane + 64];
    float lb0 = lb[lane], lb1 = lb[lane + 32], lb2 = lb[lane + 64];
    float sc0 = 1.f, sc1 = 1.f, sc2 = 1.f;
    float sh0 = 0.f, sh1 = 0.f, sh2 = 0.f;
    if (sc != nullptr) {
        sc0 = sc[lane]; sc1 = sc[lane + 32]; sc2 = sc[lane + 64];
        sh0 = sh[lane]; sh1 = sh[lane + 32]; sh2 = sh[lane + 64];
    }

    for (;;) {
        int node;
        if (lane == 0) node = atomicAdd(ctr, 1);
        node = __shfl_sync(0xffffffff, node, 0);
        if (node >= NN) return;

        int s0 = row_start[node];
        int d  = deg[node];

        float a0 = 0.f, a1 = 0.f, a2 = 0.f;
        int e = 0;
        for (; e + 4 <= d; e += 4) {
            int2 ed[4];
#pragma unroll
            for (int j = 0; j < 4; j++) ed[j] = __ldg(csr + s0 + e + j);
            float x0[4], x1[4], x2[4];
#pragma unroll
            for (int j = 0; j < 4; j++) {
                const float* xr = xin + (size_t)ed[j].x * 96;
                x0[j] = __ldg(xr + lane);
                x1[j] = __ldg(xr + lane + 32);
                x2[j] = __ldg(xr + lane + 64);
            }
#pragma unroll
            for (int j = 0; j < 4; j++) {
                float a = __int_as_float(ed[j].y);
                a0 += fmaxf(fmaf(x0[j], sc0, sh0) + fmaf(a, lw0, lb0), 0.f);
                a1 += fmaxf(fmaf(x1[j], sc1, sh1) + fmaf(a, lw1, lb1), 0.f);
                a2 += fmaxf(fmaf(x2[j], sc2, sh2) + fmaf(a, lw2, lb2), 0.f);
            }
        }
        for (; e < d; e++) {
            int2 ed = __ldg(csr + s0 + e);
            float a = __int_as_float(ed.y);
            const float* xr = xin + (size_t)ed.x * 96;
            a0 += fmaxf(fmaf(__ldg(xr + lane),      sc0, sh0) + fmaf(a, lw0, lb0), 0.f);
            a1 += fmaxf(fmaf(__ldg(xr + lane + 32), sc1, sh1) + fmaf(a, lw1, lb1), 0.f);
            a2 += fmaxf(fmaf(__ldg(xr + lane + 64), sc2, sh2) + fmaf(a, lw2, lb2), 0.f);
        }
        float* ar = agg + (size_t)node * 96;
        ar[lane]      = a0;
        ar[lane + 32] = a1;
        ar[lane + 64] = a2;
    }
}

// ================= scalar FFMA GEMM: resident W + double-buffered A =================
// H = relu( In[M,K] @ W[K,BN] + bias ); In = affine(A)(+Aadd) | affine2(B2) concat.
template<int BN, int TX, int TY, int TM, int K>
__global__ void __launch_bounds__(TX * TY)
gemm_kernel(const float* __restrict__ A,
            const float* __restrict__ scA,
            const float* __restrict__ shA,
            const float* __restrict__ Aadd,
            const float* __restrict__ B2,
            const float* __restrict__ scB,
            const float* __restrict__ shB,
            int K1,
            const float* __restrict__ W,
            const float* __restrict__ bias,
            float* __restrict__ H,
            float* __restrict__ stats,   // [sum(96) | sq(96)]
            int M)
{
    constexpr int BK = 32;
    constexpr int BM = TY * TM;
    constexpr int THREADS = TX * TY;
    constexpr int S = BM + 4;
    constexpr int NCHUNK = K / BK;

    __shared__ float At[2][BK][S];
    __shared__ float Wt[K][BN];
    __shared__ float s_sum[BN];
    __shared__ float s_sq [BN];

    const int tid = threadIdx.x;
    const int tx  = tid % TX;
    const int ty  = tid / TX;
    const int m0  = blockIdx.x * BM;
    const int K2  = K - K1;

    for (int t = tid; t < BN; t += THREADS) { s_sum[t] = 0.f; s_sq[t] = 0.f; }

    // ---- load full W once ----
    for (int t = tid; t < K * (BN / 4); t += THREADS) {
        int k  = t / (BN / 4);
        int c4 = (t % (BN / 4)) * 4;
        float4 v = *reinterpret_cast<const float4*>(W + (size_t)k * BN + c4);
        *reinterpret_cast<float4*>(&Wt[k][c4]) = v;
    }

    auto loadA = [&](int kb, float (*buf)[S]) {
        for (int t = tid; t < BM * (BK / 4); t += THREADS) {
            int m  = t >> 3;
            int k4 = (t & 7) * 4;
            int row = m0 + m;
            float4 v = make_float4(0.f, 0.f, 0.f, 0.f);
            if (row < M) {
                int gc = kb + k4;
                if (B2 != nullptr && gc >= K1) {
                    int c2 = gc - K1;
                    v = *reinterpret_cast<const float4*>(B2 + (size_t)row * K2 + c2);
                    if (scB != nullptr) {
                        float4 sc4 = *reinterpret_cast<const float4*>(scB + c2);
                        float4 sh4 = *reinterpret_cast<const float4*>(shB + c2);
                        v.x = fmaf(v.x, sc4.x, sh4.x);
                        v.y = fmaf(v.y, sc4.y, sh4.y);
                        v.z = fmaf(v.z, sc4.z, sh4.z);
                        v.w = fmaf(v.w, sc4.w, sh4.w);
                    }
                } else {
                    v = *reinterpret_cast<const float4*>(A + (size_t)row * K1 + gc);
                    if (scA != nullptr) {
                        float4 sc4 = *reinterpret_cast<const float4*>(scA + gc);
                        float4 sh4 = *reinterpret_cast<const float4*>(shA + gc);
                        v.x = fmaf(v.x, sc4.x, sh4.x);
                        v.y = fmaf(v.y, sc4.y, sh4.y);
                        v.z = fmaf(v.z, sc4.z, sh4.z);
                        v.w = fmaf(v.w, sc4.w, sh4.w);
                    }
                    if (Aadd != nullptr) {
                        float4 v2 = *reinterpret_cast<const float4*>(Aadd + (size_t)row * K1 + gc);
                        v.x += v2.x; v.y += v2.y; v.z += v2.z; v.w += v2.w;
                    }
                }
            }
            buf[k4 + 0][m] = v.x;
            buf[k4 + 1][m] = v.y;
            buf[k4 + 2][m] = v.z;
            buf[k4 + 3][m] = v.w;
        }
    };

    float acc[TM][4];
#pragma unroll
    for (int i = 0; i < TM; i++) { acc[i][0]=0.f; acc[i][1]=0.f; acc[i][2]=0.f; acc[i][3]=0.f; }

    loadA(0, At[0]);
    __syncthreads();

#pragma unroll
    for (int c = 0; c < NCHUNK; c++) {
        const int cur = c & 1;
        if (c + 1 < NCHUNK) loadA((c + 1) * BK, At[cur ^ 1]);

#pragma unroll 8
        for (int k = 0; k < BK; k++) {
            float4 wv = *reinterpret_cast<const float4*>(&Wt[c * BK + k][tx * 4]);
            float av[TM];
            if constexpr (TM % 4 == 0) {
#pragma unroll
                for (int ii = 0; ii < TM / 4; ii++) {
                    float4 a4 = *reinterpret_cast<const float4*>(&At[cur][k][ty * TM + ii * 4]);
                    av[ii*4+0] = a4.x; av[ii*4+1] = a4.y; av[ii*4+2] = a4.z; av[ii*4+3] = a4.w;
                }
            } else {
                float2 a2 = *reinterpret_cast<const float2*>(&At[cur][k][ty * TM]);
                av[0] = a2.x; av[1] = a2.y;
            }
#pragma unroll
            for (int i = 0; i < TM; i++) {
                acc[i][0] = fmaf(av[i], wv.x, acc[i][0]);
                acc[i][1] = fmaf(av[i], wv.y, acc[i][1]);
                acc[i][2] = fmaf(av[i], wv.z, acc[i][2]);
                acc[i][3] = fmaf(av[i], wv.w, acc[i][3]);
            }
        }
        __syncthreads();
    }

    // ---- epilogue: bias + relu + store + BN stats ----
    float4 b4 = *reinterpret_cast<const float4*>(bias + tx * 4);
    float csum[4] = {0.f, 0.f, 0.f, 0.f};
    float csq [4] = {0.f, 0.f, 0.f, 0.f};
#pragma unroll
    for (int i = 0; i < TM; i++) {
        int row = m0 + ty * TM + i;
        if (row < M) {
            float4 o;
            o.x = fmaxf(acc[i][0] + b4.x, 0.f);
            o.y = fmaxf(acc[i][1] + b4.y, 0.f);
            o.z = fmaxf(acc[i][2] + b4.z, 0.f);
            o.w = fmaxf(acc[i][3] + b4.w, 0.f);
            *reinterpret_cast<float4*>(H + (size_t)row * BN + tx * 4) = o;
            csum[0] += o.x; csum[1] += o.y; csum[2] += o.z; csum[3] += o.w;
            csq [0] += o.x * o.x; csq[1] += o.y * o.y; csq[2] += o.z * o.z; csq[3] += o.w * o.w;
        }
    }
    atomicAdd(&s_sum[tx * 4 + 0], csum[0]);
    atomicAdd(&s_sum[tx * 4 + 1], csum[1]);
    atomicAdd(&s_sum[tx * 4 + 2], csum[2]);
    atomicAdd(&s_sum[tx * 4 + 3], csum[3]);
    atomicAdd(&s_sq [tx * 4 + 0], csq[0]);
    atomicAdd(&s_sq [tx * 4 + 1], csq[1]);
    atomicAdd(&s_sq [tx * 4 + 2], csq[2]);
    atomicAdd(&s_sq [tx * 4 + 3], csq[3]);
    __syncthreads();
    for (int t = tid; t < BN; t += THREADS) {
        atomicAdd(stats + t,      s_sum[t]);
        atomicAdd(stats + 96 + t, s_sq[t]);
    }
}

// ================= BN finalize =================
__global__ void finalize_kernel(const float* __restrict__ stats,
                                const float* __restrict__ g,
                                const float* __restrict__ beta,
                                float* __restrict__ scale,
                                float* __restrict__ shift,
                                int BNc, int M)
{
    int t = threadIdx.x;
    if (t < BNc) {
        float invM = 1.0f / (float)M;
        float mu   = stats[t] * invM;
        float var  = stats[96 + t] * invM - mu * mu;
        float inv  = rsqrtf(var + 1e-5f);
        float sc   = g[t] * inv;
        scale[t] = sc;
        shift[t] = fmaf(-mu, sc, beta[t]);
    }
}

// ================= final output normalize =================
__global__ void norm_kernel(const float* __restrict__ Hin,
                            const float* __restrict__ scale,
                            const float* __restrict__ shift,
                            float* __restrict__ out, int n4, int cols4)
{
    int i = blockIdx.x * blockDim.x + threadIdx.x;
    if (i >= n4) return;
    int c4 = (i % cols4) * 4;
    float4 v  = reinterpret_cast<const float4*>(Hin)[i];
    float4 sc = *reinterpret_cast<const float4*>(scale + c4);
    float4 sh = *reinterpret_cast<const float4*>(shift + c4);
    float4 r;
    r.x = fmaf(v.x, sc.x, sh.x);
    r.y = fmaf(v.y, sc.y, sh.y);
    r.z = fmaf(v.z, sc.z, sh.z);
    r.w = fmaf(v.w, sc.w, sh.w);
    reinterpret_cast<float4*>(out)[i] = r;
}

// ================= host =================
extern "C" void kernel_launch(void* const* d_in, const int* in_sizes, int n_in,
                              void* d_out, int out_size)
{
    const float* x   = (const float*)d_in[0];
    const float* ea  = (const float*)d_in[1];
    const int*   ei  = (const int*)  d_in[2];
    const float* lw  = (const float*)d_in[3];
    const float* lb  = (const float*)d_in[4];
    const float* w1  = (const float*)d_in[5];
    const float* b1  = (const float*)d_in[6];
    const float* g1  = (const float*)d_in[7];
    const float* be1 = (const float*)d_in[8];
    const float* w2  = (const float*)d_in[9];
    const float* b2  = (const float*)d_in[10];
    const float* g2  = (const float*)d_in[11];
    const float* be2 = (const float*)d_in[12];
    const float* w3  = (const float*)d_in[13];
    const float* b3  = (const float*)d_in[14];
    const float* g3  = (const float*)d_in[15];
    const float* be3 = (const float*)d_in[16];
    const float* w4  = (const float*)d_in[17];
    const float* b4  = (const float*)d_in[18];
    const float* g4  = (const float*)d_in[19];
    const float* be4 = (const float*)d_in[20];
    const float* w5  = (const float*)d_in[21];
    const float* b5  = (const float*)d_in[22];
    const float* g5  = (const float*)d_in[23];
    const float* be5 = (const float*)d_in[24];
    float* out = (float*)d_out;

    const int* srcp = ei;
    const int* dstp = ei + NE;

    float *agg, *h1, *h2, *h3, *h4, *h5, *stats, *scb, *shb;
    int *deg, *row_start, *pos, *ctr;
    int2 *csr;
    cudaGetSymbolAddress((void**)&agg,       g_agg);
    cudaGetSymbolAddress((void**)&h1,        g_h1);
    cudaGetSymbolAddress((void**)&h2,        g_h2);
    cudaGetSymbolAddress((void**)&h3,        g_h3);
    cudaGetSymbolAddress((void**)&h4,        g_h4);
    cudaGetSymbolAddress((void**)&h5,        g_h5);
    cudaGetSymbolAddress((void**)&stats,     g_stats);
    cudaGetSymbolAddress((void**)&scb,       g_sc);
    cudaGetSymbolAddress((void**)&shb,       g_sh);
    cudaGetSymbolAddress((void**)&deg,       g_deg);
    cudaGetSymbolAddress((void**)&row_start, g_row_start);
    cudaGetSymbolAddress((void**)&pos,       g_pos);
    cudaGetSymbolAddress((void**)&csr,       g_csr);
    cudaGetSymbolAddress((void**)&ctr,       g_ctr);

    float* st1 = stats + 0 * 192;
    float* st2 = stats + 1 * 192;
    float* st3 = stats + 2 * 192;
    float* st4 = stats + 3 * 192;
    float* st5 = stats + 4 * 192;
    float* sc1 = scb + 0 * 96; float* sh1 = shb + 0 * 96;
    float* sc2 = scb + 1 * 96; float* sh2 = shb + 1 * 96;
    float* sc3 = scb + 2 * 96; float* sh3 = shb + 2 * 96;
    float* sc4 = scb + 3 * 96; float* sh4 = shb + 3 * 96;
    float* sc5 = scb + 4 * 96; float* sh5 = shb + 4 * 96;

    const int M = NN;
    const int eblk = (NE + 255) / 256;
    const int awsblocks = 148 * 8;       // persistent work-stealing grid
    const int gb128 = (M + 127) / 128;   // 391
    const int gb64  = (M + 63) / 64;

    cudaMemsetAsync(deg, 0, NN * sizeof(int), 0);
    hist_kernel<<<eblk, 256>>>(dstp, deg);
    scan_kernel<<<1, 1024>>>(deg, row_start, pos, stats, ctr);
    scatter_kernel<<<eblk, 256>>>(srcp, dstp, ea, pos, csr);

    // ---- conv1 ----
    aggregate_kernel<<<awsblocks, 256>>>(x, nullptr, nullptr, lw, lb,
                                         row_start, deg, csr, ctr + 0, agg);
    gemm_kernel<96, 24, 16, 8, 96><<<gb128, 384>>>(x, nullptr, nullptr, agg,
                                                   nullptr, nullptr, nullptr, 96,
                                                   w1, b1, h1, st1, M);
    finalize_kernel<<<1, 96>>>(st1, g1, be1, sc1, sh1, 96, M);

    // ---- conv2 ----
    aggregate_kernel<<<awsblocks, 256>>>(h1, sc1, sh1, lw, lb,
                                         row_start, deg, csr, ctr + 1, agg);
    gemm_kernel<64, 16, 16, 8, 96><<<gb128, 256>>>(h1, sc1, sh1, agg,
                                                   nullptr, nullptr, nullptr, 96,
                                                   w2, b2, h2, st2, M);
    finalize_kernel<<<1, 64>>>(st2, g2, be2, sc2, sh2, 64, M);

    // ---- lin1: concat(affine(h1), affine(h2)) @ w3 ----
    gemm_kernel<96, 24, 16, 8, 160><<<gb128, 384>>>(h1, sc1, sh1, nullptr,
                                                    h2, sc2, sh2, 96,
                                                    w3, b3, h3, st3, M);
    finalize_kernel<<<1, 96>>>(st3, g3, be3, sc3, sh3, 96, M);

    // ---- mlp1a ----
    gemm_kernel<96, 24, 16, 8, 96><<<gb128, 384>>>(h3, sc3, sh3, nullptr,
                                                   nullptr, nullptr, nullptr, 96,
                                                   w4, b4, h4, st4, M);
    finalize_kernel<<<1, 96>>>(st4, g4, be4, sc4, sh4, 96, M);

    // ---- mlp1b -> output ----
    gemm_kernel<16, 4, 32, 2, 96><<<gb64, 128>>>(h4, sc4, sh4, nullptr,
                                                 nullptr, nullptr, nullptr, 96,
                                                 w5, b5, h5, st5, M);
    finalize_kernel<<<1, 16>>>(st5, g5, be5, sc5, sh5, 16, M);
    norm_kernel<<<(M * 4 + 255) / 256, 256>>>(h5, sc5, sh5, out, M * 4, 4);

    (void)in_sizes; (void)n_in; (void)out_size;
}

// round 15
// speedup vs baseline: 1.0745x; 1.0745x over previous
#include <cuda_runtime.h>
#include <cstdint>

#define NN 50000
#define NE 800000

// ================= scratch =================
__device__ __align__(16) float g_agg[NN * 96];
__device__ __align__(16) float g_h1 [NN * 96];
__device__ __align__(16) float g_h2 [NN * 64];
__device__ __align__(16) float g_h3 [NN * 96];
__device__ __align__(16) float g_h4 [NN * 96];
__device__ __align__(16) float g_h5 [NN * 16];
__device__ __align__(16) float g_stats[5][192];   // [layer][sum(96) | sq(96)]
__device__ __align__(16) float g_sc [5][96];
__device__ __align__(16) float g_sh [5][96];
// CSR scratch (src index + edge attr packed)
__device__ int   g_deg      [NN];
__device__ int   g_row_start[NN];
__device__ int   g_pos      [NN];
__device__ __align__(8) int2 g_csr[NE];           // {src, float_as_int(ea)}

// ================= CSR build =================
__global__ void hist_kernel(const int* __restrict__ dst, int* __restrict__ deg)
{
    int i = blockIdx.x * blockDim.x + threadIdx.x;
    if (i < NE) atomicAdd(&deg[dst[i]], 1);
}

// scan also zeroes the BN stats buffers
__global__ void scan_kernel(const int* __restrict__ deg,
                            int* __restrict__ row_start,
                            int* __restrict__ pos,
                            float* __restrict__ stats)
{
    constexpr int T = 1024;
    constexpr int CH = (NN + T - 1) / T;
    __shared__ int warp_sums[32];
    int t = threadIdx.x;
    int base = t * CH;

    if (t < 5 * 192 / 2) reinterpret_cast<float2*>(stats)[t] = make_float2(0.f, 0.f);

    int s = 0;
    for (int i = 0; i < CH; i++) {
        int idx = base + i;
        if (idx < NN) s += deg[idx];
    }
    int lane = t & 31, wid = t >> 5;
    int v = s;
#pragma unroll
    for (int o = 1; o < 32; o <<= 1) {
        int u = __shfl_up_sync(0xffffffff, v, o);
        if (lane >= o) v += u;
    }
    if (lane == 31) warp_sums[wid] = v;
    __syncthreads();
    if (wid == 0) {
        int w = warp_sums[lane];
#pragma unroll
        for (int o = 1; o < 32; o <<= 1) {
            int u = __shfl_up_sync(0xffffffff, w, o);
            if (lane >= o) w += u;
        }
        warp_sums[lane] = w;
    }
    __syncthreads();
    int excl = v - s + (wid > 0 ? warp_sums[wid - 1] : 0);

    int running = excl;
    for (int i = 0; i < CH; i++) {
        int idx = base + i;
        if (idx < NN) {
            row_start[idx] = running;
            pos[idx]       = running;
            running += deg[idx];
        }
    }
}

__global__ void scatter_kernel(const int* __restrict__ src,
                               const int* __restrict__ dst,
                               const float* __restrict__ ea,
                               int* __restrict__ pos,
                               int2* __restrict__ csr)
{
    int i = blockIdx.x * blockDim.x + threadIdx.x;
    if (i >= NE) return;
    int slot = atomicAdd(&pos[dst[i]], 1);
    csr[slot] = make_int2(src[i], __float_as_int(ea[i]));
}

// ================= static CSR gather aggregation (R13, proven) =================
__global__ void __launch_bounds__(256)
aggregate_kernel(const float* __restrict__ xin,
                 const float* __restrict__ sc,
                 const float* __restrict__ sh,
                 const float* __restrict__ lw,
                 const float* __restrict__ lb,
                 const int* __restrict__ row_start,
                 const int* __restrict__ deg,
                 const int2* __restrict__ csr,
                 float* __restrict__ agg)
{
    int w    = threadIdx.x >> 5;
    int lane = threadIdx.x & 31;
    int node = blockIdx.x * 8 + w;
    if (node >= NN) return;

    float lw0 = lw[lane], lw1 = lw[lane + 32], lw2 = lw[lane + 64];
    float lb0 = lb[lane], lb1 = lb[lane + 32], lb2 = lb[lane + 64];
    float sc0 = 1.f, sc1 = 1.f, sc2 = 1.f;
    float sh0 = 0.f, sh1 = 0.f, sh2 = 0.f;
    if (sc != nullptr) {
        sc0 = sc[lane]; sc1 = sc[lane + 32]; sc2 = sc[lane + 64];
        sh0 = sh[lane]; sh1 = sh[lane + 32]; sh2 = sh[lane + 64];
    }

    int s0 = row_start[node];
    int d  = deg[node];

    float a0 = 0.f, a1 = 0.f, a2 = 0.f;
    int e = 0;
    for (; e + 4 <= d; e += 4) {
        int2 ed[4];
#pragma unroll
        for (int j = 0; j < 4; j++) ed[j] = __ldg(csr + s0 + e + j);
        float x0[4], x1[4], x2[4];
#pragma unroll
        for (int j = 0; j < 4; j++) {
            const float* xr = xin + (size_t)ed[j].x * 96;
            x0[j] = __ldg(xr + lane);
            x1[j] = __ldg(xr + lane + 32);
            x2[j] = __ldg(xr + lane + 64);
        }
#pragma unroll
        for (int j = 0; j < 4; j++) {
            float a = __int_as_float(ed[j].y);
            a0 += fmaxf(fmaf(x0[j], sc0, sh0) + fmaf(a, lw0, lb0), 0.f);
            a1 += fmaxf(fmaf(x1[j], sc1, sh1) + fmaf(a, lw1, lb1), 0.f);
            a2 += fmaxf(fmaf(x2[j], sc2, sh2) + fmaf(a, lw2, lb2), 0.f);
        }
    }
    for (; e < d; e++) {
        int2 ed = __ldg(csr + s0 + e);
        float a = __int_as_float(ed.y);
        const float* xr = xin + (size_t)ed.x * 96;
        a0 += fmaxf(fmaf(__ldg(xr + lane),      sc0, sh0) + fmaf(a, lw0, lb0), 0.f);
        a1 += fmaxf(fmaf(__ldg(xr + lane + 32), sc1, sh1) + fmaf(a, lw1, lb1), 0.f);
        a2 += fmaxf(fmaf(__ldg(xr + lane + 64), sc2, sh2) + fmaf(a, lw2, lb2), 0.f);
    }
    float* ar = agg + (size_t)node * 96;
    ar[lane]      = a0;
    ar[lane + 32] = a1;
    ar[lane + 64] = a2;
}

// ================= scalar FFMA GEMM: resident W + double-buffered A (R14 shape) =================
// H = relu( In[M,K] @ W[K,BN] + bias ); In = affine(A)(+Aadd) | affine2(B2) concat.
template<int BN, int TX, int TY, int TM, int K>
__global__ void __launch_bounds__(TX * TY)
gemm_kernel(const float* __restrict__ A,
            const float* __restrict__ scA,
            const float* __restrict__ shA,
            const float* __restrict__ Aadd,
            const float* __restrict__ B2,
            const float* __restrict__ scB,
            const float* __restrict__ shB,
            int K1,
            const float* __restrict__ W,
            const float* __restrict__ bias,
            float* __restrict__ H,
            float* __restrict__ stats,   // [sum(96) | sq(96)]
            int M)
{
    constexpr int BK = 32;
    constexpr int BM = TY * TM;
    constexpr int THREADS = TX * TY;
    constexpr int S = BM + 4;
    constexpr int NCHUNK = K / BK;

    __shared__ float At[2][BK][S];
    __shared__ float Wt[K][BN];
    __shared__ float s_sum[BN];
    __shared__ float s_sq [BN];

    const int tid = threadIdx.x;
    const int tx  = tid % TX;
    const int ty  = tid / TX;
    const int m0  = blockIdx.x * BM;
    const int K2  = K - K1;

    for (int t = tid; t < BN; t += THREADS) { s_sum[t] = 0.f; s_sq[t] = 0.f; }

    // ---- load full W once ----
    for (int t = tid; t < K * (BN / 4); t += THREADS) {
        int k  = t / (BN / 4);
        int c4 = (t % (BN / 4)) * 4;
        float4 v = *reinterpret_cast<const float4*>(W + (size_t)k * BN + c4);
        *reinterpret_cast<float4*>(&Wt[k][c4]) = v;
    }

    auto loadA = [&](int kb, float (*buf)[S]) {
        for (int t = tid; t < BM * (BK / 4); t += THREADS) {
            int m  = t >> 3;
            int k4 = (t & 7) * 4;
            int row = m0 + m;
            float4 v = make_float4(0.f, 0.f, 0.f, 0.f);
            if (row < M) {
                int gc = kb + k4;
                if (B2 != nullptr && gc >= K1) {
                    int c2 = gc - K1;
                    v = *reinterpret_cast<const float4*>(B2 + (size_t)row * K2 + c2);
                    if (scB != nullptr) {
                        float4 sc4 = *reinterpret_cast<const float4*>(scB + c2);
                        float4 sh4 = *reinterpret_cast<const float4*>(shB + c2);
                        v.x = fmaf(v.x, sc4.x, sh4.x);
                        v.y = fmaf(v.y, sc4.y, sh4.y);
                        v.z = fmaf(v.z, sc4.z, sh4.z);
                        v.w = fmaf(v.w, sc4.w, sh4.w);
                    }
                } else {
                    v = *reinterpret_cast<const float4*>(A + (size_t)row * K1 + gc);
                    if (scA != nullptr) {
                        float4 sc4 = *reinterpret_cast<const float4*>(scA + gc);
                        float4 sh4 = *reinterpret_cast<const float4*>(shA + gc);
                        v.x = fmaf(v.x, sc4.x, sh4.x);
                        v.y = fmaf(v.y, sc4.y, sh4.y);
                        v.z = fmaf(v.z, sc4.z, sh4.z);
                        v.w = fmaf(v.w, sc4.w, sh4.w);
                    }
                    if (Aadd != nullptr) {
                        float4 v2 = *reinterpret_cast<const float4*>(Aadd + (size_t)row * K1 + gc);
                        v.x += v2.x; v.y += v2.y; v.z += v2.z; v.w += v2.w;
                    }
                }
            }
            buf[k4 + 0][m] = v.x;
            buf[k4 + 1][m] = v.y;
            buf[k4 + 2][m] = v.z;
            buf[k4 + 3][m] = v.w;
        }
    };

    float acc[TM][4];
#pragma unroll
    for (int i = 0; i < TM; i++) { acc[i][0]=0.f; acc[i][1]=0.f; acc[i][2]=0.f; acc[i][3]=0.f; }

    loadA(0, At[0]);
    __syncthreads();

#pragma unroll
    for (int c = 0; c < NCHUNK; c++) {
        const int cur = c & 1;
        if (c + 1 < NCHUNK) loadA((c + 1) * BK, At[cur ^ 1]);

#pragma unroll 8
        for (int k = 0; k < BK; k++) {
            float4 wv = *reinterpret_cast<const float4*>(&Wt[c * BK + k][tx * 4]);
            float av[TM];
            if constexpr (TM % 4 == 0) {
#pragma unroll
                for (int ii = 0; ii < TM / 4; ii++) {
                    float4 a4 = *reinterpret_cast<const float4*>(&At[cur][k][ty * TM + ii * 4]);
                    av[ii*4+0] = a4.x; av[ii*4+1] = a4.y; av[ii*4+2] = a4.z; av[ii*4+3] = a4.w;
                }
            } else {
                float2 a2 = *reinterpret_cast<const float2*>(&At[cur][k][ty * TM]);
                av[0] = a2.x; av[1] = a2.y;
            }
#pragma unroll
            for (int i = 0; i < TM; i++) {
                acc[i][0] = fmaf(av[i], wv.x, acc[i][0]);
                acc[i][1] = fmaf(av[i], wv.y, acc[i][1]);
                acc[i][2] = fmaf(av[i], wv.z, acc[i][2]);
                acc[i][3] = fmaf(av[i], wv.w, acc[i][3]);
            }
        }
        __syncthreads();
    }

    // ---- epilogue: bias + relu + store + BN stats ----
    float4 b4 = *reinterpret_cast<const float4*>(bias + tx * 4);
    float csum[4] = {0.f, 0.f, 0.f, 0.f};
    float csq [4] = {0.f, 0.f, 0.f, 0.f};
#pragma unroll
    for (int i = 0; i < TM; i++) {
        int row = m0 + ty * TM + i;
        if (row < M) {
            float4 o;
            o.x = fmaxf(acc[i][0] + b4.x, 0.f);
            o.y = fmaxf(acc[i][1] + b4.y, 0.f);
            o.z = fmaxf(acc[i][2] + b4.z, 0.f);
            o.w = fmaxf(acc[i][3] + b4.w, 0.f);
            *reinterpret_cast<float4*>(H + (size_t)row * BN + tx * 4) = o;
            csum[0] += o.x; csum[1] += o.y; csum[2] += o.z; csum[3] += o.w;
            csq [0] += o.x * o.x; csq[1] += o.y * o.y; csq[2] += o.z * o.z; csq[3] += o.w * o.w;
        }
    }
    atomicAdd(&s_sum[tx * 4 + 0], csum[0]);
    atomicAdd(&s_sum[tx * 4 + 1], csum[1]);
    atomicAdd(&s_sum[tx * 4 + 2], csum[2]);
    atomicAdd(&s_sum[tx * 4 + 3], csum[3]);
    atomicAdd(&s_sq [tx * 4 + 0], csq[0]);
    atomicAdd(&s_sq [tx * 4 + 1], csq[1]);
    atomicAdd(&s_sq [tx * 4 + 2], csq[2]);
    atomicAdd(&s_sq [tx * 4 + 3], csq[3]);
    __syncthreads();
    for (int t = tid; t < BN; t += THREADS) {
        atomicAdd(stats + t,      s_sum[t]);
        atomicAdd(stats + 96 + t, s_sq[t]);
    }
}

// ================= BN finalize =================
__global__ void finalize_kernel(const float* __restrict__ stats,
                                const float* __restrict__ g,
                                const float* __restrict__ beta,
                                float* __restrict__ scale,
                                float* __restrict__ shift,
                                int BNc, int M)
{
    int t = threadIdx.x;
    if (t < BNc) {
        float invM = 1.0f / (float)M;
        float mu   = stats[t] * invM;
        float var  = stats[96 + t] * invM - mu * mu;
        float inv  = rsqrtf(var + 1e-5f);
        float sc   = g[t] * inv;
        scale[t] = sc;
        shift[t] = fmaf(-mu, sc, beta[t]);
    }
}

// ================= final output normalize =================
__global__ void norm_kernel(const float* __restrict__ Hin,
                            const float* __restrict__ scale,
                            const float* __restrict__ shift,
                            float* __restrict__ out, int n4, int cols4)
{
    int i = blockIdx.x * blockDim.x + threadIdx.x;
    if (i >= n4) return;
    int c4 = (i % cols4) * 4;
    float4 v  = reinterpret_cast<const float4*>(Hin)[i];
    float4 sc = *reinterpret_cast<const float4*>(scale + c4);
    float4 sh = *reinterpret_cast<const float4*>(shift + c4);
    float4 r;
    r.x = fmaf(v.x, sc.x, sh.x);
    r.y = fmaf(v.y, sc.y, sh.y);
    r.z = fmaf(v.z, sc.z, sh.z);
    r.w = fmaf(v.w, sc.w, sh.w);
    reinterpret_cast<float4*>(out)[i] = r;
}

// ================= host =================
extern "C" void kernel_launch(void* const* d_in, const int* in_sizes, int n_in,
                              void* d_out, int out_size)
{
    const float* x   = (const float*)d_in[0];
    const float* ea  = (const float*)d_in[1];
    const int*   ei  = (const int*)  d_in[2];
    const float* lw  = (const float*)d_in[3];
    const float* lb  = (const float*)d_in[4];
    const float* w1  = (const float*)d_in[5];
    const float* b1  = (const float*)d_in[6];
    const float* g1  = (const float*)d_in[7];
    const float* be1 = (const float*)d_in[8];
    const float* w2  = (const float*)d_in[9];
    const float* b2  = (const float*)d_in[10];
    const float* g2  = (const float*)d_in[11];
    const float* be2 = (const float*)d_in[12];
    const float* w3  = (const float*)d_in[13];
    const float* b3  = (const float*)d_in[14];
    const float* g3  = (const float*)d_in[15];
    const float* be3 = (const float*)d_in[16];
    const float* w4  = (const float*)d_in[17];
    const float* b4  = (const float*)d_in[18];
    const float* g4  = (const float*)d_in[19];
    const float* be4 = (const float*)d_in[20];
    const float* w5  = (const float*)d_in[21];
    const float* b5  = (const float*)d_in[22];
    const float* g5  = (const float*)d_in[23];
    const float* be5 = (const float*)d_in[24];
    float* out = (float*)d_out;

    const int* srcp = ei;
    const int* dstp = ei + NE;

    float *agg, *h1, *h2, *h3, *h4, *h5, *stats, *scb, *shb;
    int *deg, *row_start, *pos;
    int2 *csr;
    cudaGetSymbolAddress((void**)&agg,       g_agg);
    cudaGetSymbolAddress((void**)&h1,        g_h1);
    cudaGetSymbolAddress((void**)&h2,        g_h2);
    cudaGetSymbolAddress((void**)&h3,        g_h3);
    cudaGetSymbolAddress((void**)&h4,        g_h4);
    cudaGetSymbolAddress((void**)&h5,        g_h5);
    cudaGetSymbolAddress((void**)&stats,     g_stats);
    cudaGetSymbolAddress((void**)&scb,       g_sc);
    cudaGetSymbolAddress((void**)&shb,       g_sh);
    cudaGetSymbolAddress((void**)&deg,       g_deg);
    cudaGetSymbolAddress((void**)&row_start, g_row_start);
    cudaGetSymbolAddress((void**)&pos,       g_pos);
    cudaGetSymbolAddress((void**)&csr,       g_csr);

    float* st1 = stats + 0 * 192;
    float* st2 = stats + 1 * 192;
    float* st3 = stats + 2 * 192;
    float* st4 = stats + 3 * 192;
    float* st5 = stats + 4 * 192;
    float* sc1 = scb + 0 * 96; float* sh1 = shb + 0 * 96;
    float* sc2 = scb + 1 * 96; float* sh2 = shb + 1 * 96;
    float* sc3 = scb + 2 * 96; float* sh3 = shb + 2 * 96;
    float* sc4 = scb + 3 * 96; float* sh4 = shb + 3 * 96;
    float* sc5 = scb + 4 * 96; float* sh5 = shb + 4 * 96;

    const int M = NN;
    const int eblk = (NE + 255) / 256;
    const int ablocks = (NN + 7) / 8;
    const int gb128 = (M + 127) / 128;   // 391
    const int gb64  = (M + 63) / 64;

    cudaMemsetAsync(deg, 0, NN * sizeof(int), 0);
    hist_kernel<<<eblk, 256>>>(dstp, deg);
    scan_kernel<<<1, 1024>>>(deg, row_start, pos, stats);
    scatter_kernel<<<eblk, 256>>>(srcp, dstp, ea, pos, csr);

    // ---- conv1 ----
    aggregate_kernel<<<ablocks, 256>>>(x, nullptr, nullptr, lw, lb,
                                       row_start, deg, csr, agg);
    gemm_kernel<96, 24, 16, 8, 96><<<gb128, 384>>>(x, nullptr, nullptr, agg,
                                                   nullptr, nullptr, nullptr, 96,
                                                   w1, b1, h1, st1, M);
    finalize_kernel<<<1, 96>>>(st1, g1, be1, sc1, sh1, 96, M);

    // ---- conv2 ----
    aggregate_kernel<<<ablocks, 256>>>(h1, sc1, sh1, lw, lb,
                                       row_start, deg, csr, agg);
    gemm_kernel<64, 16, 16, 8, 96><<<gb128, 256>>>(h1, sc1, sh1, agg,
                                                   nullptr, nullptr, nullptr, 96,
                                                   w2, b2, h2, st2, M);
    finalize_kernel<<<1, 64>>>(st2, g2, be2, sc2, sh2, 64, M);

    // ---- lin1: concat(affine(h1), affine(h2)) @ w3 ----
    gemm_kernel<96, 24, 16, 8, 160><<<gb128, 384>>>(h1, sc1, sh1, nullptr,
                                                    h2, sc2, sh2, 96,
                                                    w3, b3, h3, st3, M);
    finalize_kernel<<<1, 96>>>(st3, g3, be3, sc3, sh3, 96, M);

    // ---- mlp1a ----
    gemm_kernel<96, 24, 16, 8, 96><<<gb128, 384>>>(h3, sc3, sh3, nullptr,
                                                   nullptr, nullptr, nullptr, 96,
                                                   w4, b4, h4, st4, M);
    finalize_kernel<<<1, 96>>>(st4, g4, be4, sc4, sh4, 96, M);

    // ---- mlp1b -> output ----
    gemm_kernel<16, 4, 32, 2, 96><<<gb64, 128>>>(h4, sc4, sh4, nullptr,
                                                 nullptr, nullptr, nullptr, 96,
                                                 w5, b5, h5, st5, M);
    finalize_kernel<<<1, 16>>>(st5, g5, be5, sc5, sh5, 16, M);
    norm_kernel<<<(M * 4 + 255) / 256, 256>>>(h5, sc5, sh5, out, M * 4, 4);

    (void)in_sizes; (void)n_in; (void)out_size;
}

// round 16
// speedup vs baseline: 1.0944x; 1.0185x over previous
#include <cuda_runtime.h>
#include <cstdint>

#define NN 50000
#define NE 800000

// ================= scratch =================
__device__ __align__(16) float g_agg[NN * 96];
__device__ __align__(16) float g_h1 [NN * 96];
__device__ __align__(16) float g_h2 [NN * 64];
__device__ __align__(16) float g_h3 [NN * 96];
__device__ __align__(16) float g_h4 [NN * 96];
__device__ __align__(16) float g_h5 [NN * 16];
__device__ __align__(16) float g_stats[5][192];   // [layer][sum(96) | sq(96)]
__device__ __align__(16) float g_sc [5][96];
__device__ __align__(16) float g_sh [5][96];
// CSR scratch (src index + edge attr packed)
__device__ int   g_deg      [NN];
__device__ int   g_row_start[NN];
__device__ int   g_pos      [NN];
__device__ __align__(8) int2 g_csr[NE];           // {src, float_as_int(ea)}

// ================= CSR build =================
__global__ void hist_kernel(const int* __restrict__ dst, int* __restrict__ deg)
{
    int i = blockIdx.x * blockDim.x + threadIdx.x;
    if (i < NE) atomicAdd(&deg[dst[i]], 1);
}

// scan also zeroes the BN stats buffers
__global__ void scan_kernel(const int* __restrict__ deg,
                            int* __restrict__ row_start,
                            int* __restrict__ pos,
                            float* __restrict__ stats)
{
    constexpr int T = 1024;
    constexpr int CH = (NN + T - 1) / T;
    __shared__ int warp_sums[32];
    int t = threadIdx.x;
    int base = t * CH;

    if (t < 5 * 192 / 2) reinterpret_cast<float2*>(stats)[t] = make_float2(0.f, 0.f);

    int s = 0;
    for (int i = 0; i < CH; i++) {
        int idx = base + i;
        if (idx < NN) s += deg[idx];
    }
    int lane = t & 31, wid = t >> 5;
    int v = s;
#pragma unroll
    for (int o = 1; o < 32; o <<= 1) {
        int u = __shfl_up_sync(0xffffffff, v, o);
        if (lane >= o) v += u;
    }
    if (lane == 31) warp_sums[wid] = v;
    __syncthreads();
    if (wid == 0) {
        int w = warp_sums[lane];
#pragma unroll
        for (int o = 1; o < 32; o <<= 1) {
            int u = __shfl_up_sync(0xffffffff, w, o);
            if (lane >= o) w += u;
        }
        warp_sums[lane] = w;
    }
    __syncthreads();
    int excl = v - s + (wid > 0 ? warp_sums[wid - 1] : 0);

    int running = excl;
    for (int i = 0; i < CH; i++) {
        int idx = base + i;
        if (idx < NN) {
            row_start[idx] = running;
            pos[idx]       = running;
            running += deg[idx];
        }
    }
}

__global__ void scatter_kernel(const int* __restrict__ src,
                               const int* __restrict__ dst,
                               const float* __restrict__ ea,
                               int* __restrict__ pos,
                               int2* __restrict__ csr)
{
    int i = blockIdx.x * blockDim.x + threadIdx.x;
    if (i >= NE) return;
    int slot = atomicAdd(&pos[dst[i]], 1);
    csr[slot] = make_int2(src[i], __float_as_int(ea[i]));
}

// ================= static CSR gather aggregation (proven) =================
__global__ void __launch_bounds__(256)
aggregate_kernel(const float* __restrict__ xin,
                 const float* __restrict__ sc,
                 const float* __restrict__ sh,
                 const float* __restrict__ lw,
                 const float* __restrict__ lb,
                 const int* __restrict__ row_start,
                 const int* __restrict__ deg,
                 const int2* __restrict__ csr,
                 float* __restrict__ agg)
{
    int w    = threadIdx.x >> 5;
    int lane = threadIdx.x & 31;
    int node = blockIdx.x * 8 + w;
    if (node >= NN) return;

    float lw0 = lw[lane], lw1 = lw[lane + 32], lw2 = lw[lane + 64];
    float lb0 = lb[lane], lb1 = lb[lane + 32], lb2 = lb[lane + 64];
    float sc0 = 1.f, sc1 = 1.f, sc2 = 1.f;
    float sh0 = 0.f, sh1 = 0.f, sh2 = 0.f;
    if (sc != nullptr) {
        sc0 = sc[lane]; sc1 = sc[lane + 32]; sc2 = sc[lane + 64];
        sh0 = sh[lane]; sh1 = sh[lane + 32]; sh2 = sh[lane + 64];
    }

    int s0 = row_start[node];
    int d  = deg[node];

    float a0 = 0.f, a1 = 0.f, a2 = 0.f;
    int e = 0;
    for (; e + 4 <= d; e += 4) {
        int2 ed[4];
#pragma unroll
        for (int j = 0; j < 4; j++) ed[j] = __ldg(csr + s0 + e + j);
        float x0[4], x1[4], x2[4];
#pragma unroll
        for (int j = 0; j < 4; j++) {
            const float* xr = xin + (size_t)ed[j].x * 96;
            x0[j] = __ldg(xr + lane);
            x1[j] = __ldg(xr + lane + 32);
            x2[j] = __ldg(xr + lane + 64);
        }
#pragma unroll
        for (int j = 0; j < 4; j++) {
            float a = __int_as_float(ed[j].y);
            a0 += fmaxf(fmaf(x0[j], sc0, sh0) + fmaf(a, lw0, lb0), 0.f);
            a1 += fmaxf(fmaf(x1[j], sc1, sh1) + fmaf(a, lw1, lb1), 0.f);
            a2 += fmaxf(fmaf(x2[j], sc2, sh2) + fmaf(a, lw2, lb2), 0.f);
        }
    }
    for (; e < d; e++) {
        int2 ed = __ldg(csr + s0 + e);
        float a = __int_as_float(ed.y);
        const float* xr = xin + (size_t)ed.x * 96;
        a0 += fmaxf(fmaf(__ldg(xr + lane),      sc0, sh0) + fmaf(a, lw0, lb0), 0.f);
        a1 += fmaxf(fmaf(__ldg(xr + lane + 32), sc1, sh1) + fmaf(a, lw1, lb1), 0.f);
        a2 += fmaxf(fmaf(__ldg(xr + lane + 64), sc2, sh2) + fmaf(a, lw2, lb2), 0.f);
    }
    float* ar = agg + (size_t)node * 96;
    ar[lane]      = a0;
    ar[lane + 32] = a1;
    ar[lane + 64] = a2;
}

// ================= scalar FFMA GEMM: resident W + double-buffered A =================
// MINB = min blocks/SM hint: 3 forces regs<=56 on 384-thr variants -> single wave.
template<int BN, int TX, int TY, int TM, int K, int MINB>
__global__ void __launch_bounds__(TX * TY, MINB)
gemm_kernel(const float* __restrict__ A,
            const float* __restrict__ scA,
            const float* __restrict__ shA,
            const float* __restrict__ Aadd,
            const float* __restrict__ B2,
            const float* __restrict__ scB,
            const float* __restrict__ shB,
            int K1,
            const float* __restrict__ W,
            const float* __restrict__ bias,
            float* __restrict__ H,
            float* __restrict__ stats,   // [sum(96) | sq(96)]
            int M)
{
    constexpr int BK = 32;
    constexpr int BM = TY * TM;
    constexpr int THREADS = TX * TY;
    constexpr int S = BM + 4;
    constexpr int NCHUNK = K / BK;

    __shared__ float At[2][BK][S];
    __shared__ float Wt[K][BN];
    __shared__ float s_sum[BN];
    __shared__ float s_sq [BN];

    const int tid = threadIdx.x;
    const int tx  = tid % TX;
    const int ty  = tid / TX;
    const int m0  = blockIdx.x * BM;
    const int K2  = K - K1;

    for (int t = tid; t < BN; t += THREADS) { s_sum[t] = 0.f; s_sq[t] = 0.f; }

    // ---- load full W once ----
    for (int t = tid; t < K * (BN / 4); t += THREADS) {
        int k  = t / (BN / 4);
        int c4 = (t % (BN / 4)) * 4;
        float4 v = *reinterpret_cast<const float4*>(W + (size_t)k * BN + c4);
        *reinterpret_cast<float4*>(&Wt[k][c4]) = v;
    }

    auto loadA = [&](int kb, float (*buf)[S]) {
        for (int t = tid; t < BM * (BK / 4); t += THREADS) {
            int m  = t >> 3;
            int k4 = (t & 7) * 4;
            int row = m0 + m;
            float4 v = make_float4(0.f, 0.f, 0.f, 0.f);
            if (row < M) {
                int gc = kb + k4;
                if (B2 != nullptr && gc >= K1) {
                    int c2 = gc - K1;
                    v = *reinterpret_cast<const float4*>(B2 + (size_t)row * K2 + c2);
                    if (scB != nullptr) {
                        float4 sc4 = *reinterpret_cast<const float4*>(scB + c2);
                        float4 sh4 = *reinterpret_cast<const float4*>(shB + c2);
                        v.x = fmaf(v.x, sc4.x, sh4.x);
                        v.y = fmaf(v.y, sc4.y, sh4.y);
                        v.z = fmaf(v.z, sc4.z, sh4.z);
                        v.w = fmaf(v.w, sc4.w, sh4.w);
                    }
                } else {
                    v = *reinterpret_cast<const float4*>(A + (size_t)row * K1 + gc);
                    if (scA != nullptr) {
                        float4 sc4 = *reinterpret_cast<const float4*>(scA + gc);
                        float4 sh4 = *reinterpret_cast<const float4*>(shA + gc);
                        v.x = fmaf(v.x, sc4.x, sh4.x);
                        v.y = fmaf(v.y, sc4.y, sh4.y);
                        v.z = fmaf(v.z, sc4.z, sh4.z);
                        v.w = fmaf(v.w, sc4.w, sh4.w);
                    }
                    if (Aadd != nullptr) {
                        float4 v2 = *reinterpret_cast<const float4*>(Aadd + (size_t)row * K1 + gc);
                        v.x += v2.x; v.y += v2.y; v.z += v2.z; v.w += v2.w;
                    }
                }
            }
            buf[k4 + 0][m] = v.x;
            buf[k4 + 1][m] = v.y;
            buf[k4 + 2][m] = v.z;
            buf[k4 + 3][m] = v.w;
        }
    };

    float acc[TM][4];
#pragma unroll
    for (int i = 0; i < TM; i++) { acc[i][0]=0.f; acc[i][1]=0.f; acc[i][2]=0.f; acc[i][3]=0.f; }

    loadA(0, At[0]);
    __syncthreads();

#pragma unroll
    for (int c = 0; c < NCHUNK; c++) {
        const int cur = c & 1;
        if (c + 1 < NCHUNK) loadA((c + 1) * BK, At[cur ^ 1]);

#pragma unroll 8
        for (int k = 0; k < BK; k++) {
            float4 wv = *reinterpret_cast<const float4*>(&Wt[c * BK + k][tx * 4]);
            float av[TM];
            if constexpr (TM % 4 == 0) {
#pragma unroll
                for (int ii = 0; ii < TM / 4; ii++) {
                    float4 a4 = *reinterpret_cast<const float4*>(&At[cur][k][ty * TM + ii * 4]);
                    av[ii*4+0] = a4.x; av[ii*4+1] = a4.y; av[ii*4+2] = a4.z; av[ii*4+3] = a4.w;
                }
            } else {
                float2 a2 = *reinterpret_cast<const float2*>(&At[cur][k][ty * TM]);
                av[0] = a2.x; av[1] = a2.y;
            }
#pragma unroll
            for (int i = 0; i < TM; i++) {
                acc[i][0] = fmaf(av[i], wv.x, acc[i][0]);
                acc[i][1] = fmaf(av[i], wv.y, acc[i][1]);
                acc[i][2] = fmaf(av[i], wv.z, acc[i][2]);
                acc[i][3] = fmaf(av[i], wv.w, acc[i][3]);
            }
        }
        __syncthreads();
    }

    // ---- epilogue: bias + relu + store + BN stats ----
    float4 b4 = *reinterpret_cast<const float4*>(bias + tx * 4);
    float csum[4] = {0.f, 0.f, 0.f, 0.f};
    float csq [4] = {0.f, 0.f, 0.f, 0.f};
#pragma unroll
    for (int i = 0; i < TM; i++) {
        int row = m0 + ty * TM + i;
        if (row < M) {
            float4 o;
            o.x = fmaxf(acc[i][0] + b4.x, 0.f);
            o.y = fmaxf(acc[i][1] + b4.y, 0.f);
            o.z = fmaxf(acc[i][2] + b4.z, 0.f);
            o.w = fmaxf(acc[i][3] + b4.w, 0.f);
            *reinterpret_cast<float4*>(H + (size_t)row * BN + tx * 4) = o;
            csum[0] += o.x; csum[1] += o.y; csum[2] += o.z; csum[3] += o.w;
            csq [0] += o.x * o.x; csq[1] += o.y * o.y; csq[2] += o.z * o.z; csq[3] += o.w * o.w;
        }
    }
    atomicAdd(&s_sum[tx * 4 + 0], csum[0]);
    atomicAdd(&s_sum[tx * 4 + 1], csum[1]);
    atomicAdd(&s_sum[tx * 4 + 2], csum[2]);
    atomicAdd(&s_sum[tx * 4 + 3], csum[3]);
    atomicAdd(&s_sq [tx * 4 + 0], csq[0]);
    atomicAdd(&s_sq [tx * 4 + 1], csq[1]);
    atomicAdd(&s_sq [tx * 4 + 2], csq[2]);
    atomicAdd(&s_sq [tx * 4 + 3], csq[3]);
    __syncthreads();
    for (int t = tid; t < BN; t += THREADS) {
        atomicAdd(stats + t,      s_sum[t]);
        atomicAdd(stats + 96 + t, s_sq[t]);
    }
}

// ================= BN finalize =================
__global__ void finalize_kernel(const float* __restrict__ stats,
                                const float* __restrict__ g,
                                const float* __restrict__ beta,
                                float* __restrict__ scale,
                                float* __restrict__ shift,
                                int BNc, int M)
{
    int t = threadIdx.x;
    if (t < BNc) {
        float invM = 1.0f / (float)M;
        float mu   = stats[t] * invM;
        float var  = stats[96 + t] * invM - mu * mu;
        float inv  = rsqrtf(var + 1e-5f);
        float sc   = g[t] * inv;
        scale[t] = sc;
        shift[t] = fmaf(-mu, sc, beta[t]);
    }
}

// ================= final output normalize =================
__global__ void norm_kernel(const float* __restrict__ Hin,
                            const float* __restrict__ scale,
                            const float* __restrict__ shift,
                            float* __restrict__ out, int n4, int cols4)
{
    int i = blockIdx.x * blockDim.x + threadIdx.x;
    if (i >= n4) return;
    int c4 = (i % cols4) * 4;
    float4 v  = reinterpret_cast<const float4*>(Hin)[i];
    float4 sc = *reinterpret_cast<const float4*>(scale + c4);
    float4 sh = *reinterpret_cast<const float4*>(shift + c4);
    float4 r;
    r.x = fmaf(v.x, sc.x, sh.x);
    r.y = fmaf(v.y, sc.y, sh.y);
    r.z = fmaf(v.z, sc.z, sh.z);
    r.w = fmaf(v.w, sc.w, sh.w);
    reinterpret_cast<float4*>(out)[i] = r;
}

// ================= host =================
extern "C" void kernel_launch(void* const* d_in, const int* in_sizes, int n_in,
                              void* d_out, int out_size)
{
    const float* x   = (const float*)d_in[0];
    const float* ea  = (const float*)d_in[1];
    const int*   ei  = (const int*)  d_in[2];
    const float* lw  = (const float*)d_in[3];
    const float* lb  = (const float*)d_in[4];
    const float* w1  = (const float*)d_in[5];
    const float* b1  = (const float*)d_in[6];
    const float* g1  = (const float*)d_in[7];
    const float* be1 = (const float*)d_in[8];
    const float* w2  = (const float*)d_in[9];
    const float* b2  = (const float*)d_in[10];
    const float* g2  = (const float*)d_in[11];
    const float* be2 = (const float*)d_in[12];
    const float* w3  = (const float*)d_in[13];
    const float* b3  = (const float*)d_in[14];
    const float* g3  = (const float*)d_in[15];
    const float* be3 = (const float*)d_in[16];
    const float* w4  = (const float*)d_in[17];
    const float* b4  = (const float*)d_in[18];
    const float* g4  = (const float*)d_in[19];
    const float* be4 = (const float*)d_in[20];
    const float* w5  = (const float*)d_in[21];
    const float* b5  = (const float*)d_in[22];
    const float* g5  = (const float*)d_in[23];
    const float* be5 = (const float*)d_in[24];
    float* out = (float*)d_out;

    const int* srcp = ei;
    const int* dstp = ei + NE;

    float *agg, *h1, *h2, *h3, *h4, *h5, *stats, *scb, *shb;
    int *deg, *row_start, *pos;
    int2 *csr;
    cudaGetSymbolAddress((void**)&agg,       g_agg);
    cudaGetSymbolAddress((void**)&h1,        g_h1);
    cudaGetSymbolAddress((void**)&h2,        g_h2);
    cudaGetSymbolAddress((void**)&h3,        g_h3);
    cudaGetSymbolAddress((void**)&h4,        g_h4);
    cudaGetSymbolAddress((void**)&h5,        g_h5);
    cudaGetSymbolAddress((void**)&stats,     g_stats);
    cudaGetSymbolAddress((void**)&scb,       g_sc);
    cudaGetSymbolAddress((void**)&shb,       g_sh);
    cudaGetSymbolAddress((void**)&deg,       g_deg);
    cudaGetSymbolAddress((void**)&row_start, g_row_start);
    cudaGetSymbolAddress((void**)&pos,       g_pos);
    cudaGetSymbolAddress((void**)&csr,       g_csr);

    float* st1 = stats + 0 * 192;
    float* st2 = stats + 1 * 192;
    float* st3 = stats + 2 * 192;
    float* st4 = stats + 3 * 192;
    float* st5 = stats + 4 * 192;
    float* sc1 = scb + 0 * 96; float* sh1 = shb + 0 * 96;
    float* sc2 = scb + 1 * 96; float* sh2 = shb + 1 * 96;
    float* sc3 = scb + 2 * 96; float* sh3 = shb + 2 * 96;
    float* sc4 = scb + 3 * 96; float* sh4 = shb + 3 * 96;
    float* sc5 = scb + 4 * 96; float* sh5 = shb + 4 * 96;

    const int M = NN;
    const int eblk = (NE + 255) / 256;
    const int ablocks = (NN + 7) / 8;
    const int gb128 = (M + 127) / 128;   // 391
    const int gb64  = (M + 63) / 64;

    cudaMemsetAsync(deg, 0, NN * sizeof(int), 0);
    hist_kernel<<<eblk, 256>>>(dstp, deg);
    scan_kernel<<<1, 1024>>>(deg, row_start, pos, stats);
    scatter_kernel<<<eblk, 256>>>(srcp, dstp, ea, pos, csr);

    // ---- conv1 ----
    aggregate_kernel<<<ablocks, 256>>>(x, nullptr, nullptr, lw, lb,
                                       row_start, deg, csr, agg);
    gemm_kernel<96, 24, 16, 8, 96, 3><<<gb128, 384>>>(x, nullptr, nullptr, agg,
                                                      nullptr, nullptr, nullptr, 96,
                                                      w1, b1, h1, st1, M);
    finalize_kernel<<<1, 96>>>(st1, g1, be1, sc1, sh1, 96, M);

    // ---- conv2 ----
    aggregate_kernel<<<ablocks, 256>>>(h1, sc1, sh1, lw, lb,
                                       row_start, deg, csr, agg);
    gemm_kernel<64, 16, 16, 8, 96, 3><<<gb128, 256>>>(h1, sc1, sh1, agg,
                                                      nullptr, nullptr, nullptr, 96,
                                                      w2, b2, h2, st2, M);
    finalize_kernel<<<1, 64>>>(st2, g2, be2, sc2, sh2, 64, M);

    // ---- lin1: concat(affine(h1), affine(h2)) @ w3 ----
    gemm_kernel<96, 24, 16, 8, 160, 2><<<gb128, 384>>>(h1, sc1, sh1, nullptr,
                                                       h2, sc2, sh2, 96,
                                                       w3, b3, h3, st3, M);
    finalize_kernel<<<1, 96>>>(st3, g3, be3, sc3, sh3, 96, M);

    // ---- mlp1a ----
    gemm_kernel<96, 24, 16, 8, 96, 3><<<gb128, 384>>>(h3, sc3, sh3, nullptr,
                                                      nullptr, nullptr, nullptr, 96,
                                                      w4, b4, h4, st4, M);
    finalize_kernel<<<1, 96>>>(st4, g4, be4, sc4, sh4, 96, M);

    // ---- mlp1b -> output ----
    gemm_kernel<16, 4, 32, 2, 96, 2><<<gb64, 128>>>(h4, sc4, sh4, nullptr,
                                                    nullptr, nullptr, nullptr, 96,
                                                    w5, b5, h5, st5, M);
    finalize_kernel<<<1, 16>>>(st5, g5, be5, sc5, sh5, 16, M);
    norm_kernel<<<(M * 4 + 255) / 256, 256>>>(h5, sc5, sh5, out, M * 4, 4);

    (void)in_sizes; (void)n_in; (void)out_size;
}

// round 17
// speedup vs baseline: 1.1221x; 1.0254x over previous
#include <cuda_runtime.h>
#include <cstdint>

#define NN 50000
#define NE 800000

// ================= scratch =================
__device__ __align__(16) float g_agg[NN * 96];
__device__ __align__(16) float g_h1 [NN * 96];
__device__ __align__(16) float g_h2 [NN * 64];
__device__ __align__(16) float g_h3 [NN * 96];
__device__ __align__(16) float g_h4 [NN * 96];
__device__ __align__(16) float g_h5 [NN * 16];
__device__ __align__(16) float g_stats[5][192];   // [layer][sum(96) | sq(96)]
__device__ __align__(16) float g_sc [5][96];
__device__ __align__(16) float g_sh [5][96];
// CSR scratch (src index + edge attr packed)
__device__ int   g_deg      [NN];
__device__ int   g_row_start[NN];
__device__ int   g_pos      [NN];
__device__ __align__(8) int2 g_csr[NE];           // {src, float_as_int(ea)}

// ================= CSR build =================
__global__ void hist_kernel(const int* __restrict__ dst, int* __restrict__ deg)
{
    int i = blockIdx.x * blockDim.x + threadIdx.x;
    if (i < NE) atomicAdd(&deg[dst[i]], 1);
}

// scan also zeroes the BN stats buffers
__global__ void scan_kernel(const int* __restrict__ deg,
                            int* __restrict__ row_start,
                            int* __restrict__ pos,
                            float* __restrict__ stats)
{
    constexpr int T = 1024;
    constexpr int CH = (NN + T - 1) / T;
    __shared__ int warp_sums[32];
    int t = threadIdx.x;
    int base = t * CH;

    if (t < 5 * 192 / 2) reinterpret_cast<float2*>(stats)[t] = make_float2(0.f, 0.f);

    int s = 0;
    for (int i = 0; i < CH; i++) {
        int idx = base + i;
        if (idx < NN) s += deg[idx];
    }
    int lane = t & 31, wid = t >> 5;
    int v = s;
#pragma unroll
    for (int o = 1; o < 32; o <<= 1) {
        int u = __shfl_up_sync(0xffffffff, v, o);
        if (lane >= o) v += u;
    }
    if (lane == 31) warp_sums[wid] = v;
    __syncthreads();
    if (wid == 0) {
        int w = warp_sums[lane];
#pragma unroll
        for (int o = 1; o < 32; o <<= 1) {
            int u = __shfl_up_sync(0xffffffff, w, o);
            if (lane >= o) w += u;
        }
        warp_sums[lane] = w;
    }
    __syncthreads();
    int excl = v - s + (wid > 0 ? warp_sums[wid - 1] : 0);

    int running = excl;
    for (int i = 0; i < CH; i++) {
        int idx = base + i;
        if (idx < NN) {
            row_start[idx] = running;
            pos[idx]       = running;
            running += deg[idx];
        }
    }
}

__global__ void scatter_kernel(const int* __restrict__ src,
                               const int* __restrict__ dst,
                               const float* __restrict__ ea,
                               int* __restrict__ pos,
                               int2* __restrict__ csr)
{
    int i = blockIdx.x * blockDim.x + threadIdx.x;
    if (i >= NE) return;
    int slot = atomicAdd(&pos[dst[i]], 1);
    csr[slot] = make_int2(src[i], __float_as_int(ea[i]));
}

// ================= static CSR gather aggregation (2 nodes / 64-thread block) =================
__global__ void __launch_bounds__(64)
aggregate_kernel(const float* __restrict__ xin,
                 const float* __restrict__ sc,
                 const float* __restrict__ sh,
                 const float* __restrict__ lw,
                 const float* __restrict__ lb,
                 const int* __restrict__ row_start,
                 const int* __restrict__ deg,
                 const int2* __restrict__ csr,
                 float* __restrict__ agg)
{
    int w    = threadIdx.x >> 5;
    int lane = threadIdx.x & 31;
    int node = blockIdx.x * 2 + w;
    if (node >= NN) return;

    float lw0 = lw[lane], lw1 = lw[lane + 32], lw2 = lw[lane + 64];
    float lb0 = lb[lane], lb1 = lb[lane + 32], lb2 = lb[lane + 64];
    float sc0 = 1.f, sc1 = 1.f, sc2 = 1.f;
    float sh0 = 0.f, sh1 = 0.f, sh2 = 0.f;
    if (sc != nullptr) {
        sc0 = sc[lane]; sc1 = sc[lane + 32]; sc2 = sc[lane + 64];
        sh0 = sh[lane]; sh1 = sh[lane + 32]; sh2 = sh[lane + 64];
    }

    int s0 = row_start[node];
    int d  = deg[node];

    float a0 = 0.f, a1 = 0.f, a2 = 0.f;
    int e = 0;
    for (; e + 4 <= d; e += 4) {
        int2 ed[4];
#pragma unroll
        for (int j = 0; j < 4; j++) ed[j] = __ldg(csr + s0 + e + j);
        float x0[4], x1[4], x2[4];
#pragma unroll
        for (int j = 0; j < 4; j++) {
            const float* xr = xin + (size_t)ed[j].x * 96;
            x0[j] = __ldg(xr + lane);
            x1[j] = __ldg(xr + lane + 32);
            x2[j] = __ldg(xr + lane + 64);
        }
#pragma unroll
        for (int j = 0; j < 4; j++) {
            float a = __int_as_float(ed[j].y);
            a0 += fmaxf(fmaf(x0[j], sc0, sh0) + fmaf(a, lw0, lb0), 0.f);
            a1 += fmaxf(fmaf(x1[j], sc1, sh1) + fmaf(a, lw1, lb1), 0.f);
            a2 += fmaxf(fmaf(x2[j], sc2, sh2) + fmaf(a, lw2, lb2), 0.f);
        }
    }
    for (; e < d; e++) {
        int2 ed = __ldg(csr + s0 + e);
        float a = __int_as_float(ed.y);
        const float* xr = xin + (size_t)ed.x * 96;
        a0 += fmaxf(fmaf(__ldg(xr + lane),      sc0, sh0) + fmaf(a, lw0, lb0), 0.f);
        a1 += fmaxf(fmaf(__ldg(xr + lane + 32), sc1, sh1) + fmaf(a, lw1, lb1), 0.f);
        a2 += fmaxf(fmaf(__ldg(xr + lane + 64), sc2, sh2) + fmaf(a, lw2, lb2), 0.f);
    }
    float* ar = agg + (size_t)node * 96;
    ar[lane]      = a0;
    ar[lane + 32] = a1;
    ar[lane + 64] = a2;
}

// ================= scalar FFMA GEMM: resident W + double-buffered A =================
template<int BN, int TX, int TY, int TM, int K, int MINB>
__global__ void __launch_bounds__(TX * TY, MINB)
gemm_kernel(const float* __restrict__ A,
            const float* __restrict__ scA,
            const float* __restrict__ shA,
            const float* __restrict__ Aadd,
            const float* __restrict__ B2,
            const float* __restrict__ scB,
            const float* __restrict__ shB,
            int K1,
            const float* __restrict__ W,
            const float* __restrict__ bias,
            float* __restrict__ H,
            float* __restrict__ stats,   // [sum(96) | sq(96)]
            int M)
{
    constexpr int BK = 32;
    constexpr int BM = TY * TM;
    constexpr int THREADS = TX * TY;
    constexpr int S = BM + 4;
    constexpr int NCHUNK = K / BK;

    __shared__ float At[2][BK][S];
    __shared__ float Wt[K][BN];
    __shared__ float s_sum[BN];
    __shared__ float s_sq [BN];

    const int tid = threadIdx.x;
    const int tx  = tid % TX;
    const int ty  = tid / TX;
    const int m0  = blockIdx.x * BM;
    const int K2  = K - K1;

    for (int t = tid; t < BN; t += THREADS) { s_sum[t] = 0.f; s_sq[t] = 0.f; }

    // ---- load full W once ----
    for (int t = tid; t < K * (BN / 4); t += THREADS) {
        int k  = t / (BN / 4);
        int c4 = (t % (BN / 4)) * 4;
        float4 v = *reinterpret_cast<const float4*>(W + (size_t)k * BN + c4);
        *reinterpret_cast<float4*>(&Wt[k][c4]) = v;
    }

    auto loadA = [&](int kb, float (*buf)[S]) {
        for (int t = tid; t < BM * (BK / 4); t += THREADS) {
            int m  = t >> 3;
            int k4 = (t & 7) * 4;
            int row = m0 + m;
            float4 v = make_float4(0.f, 0.f, 0.f, 0.f);
            if (row < M) {
                int gc = kb + k4;
                if (B2 != nullptr && gc >= K1) {
                    int c2 = gc - K1;
                    v = *reinterpret_cast<const float4*>(B2 + (size_t)row * K2 + c2);
                    if (scB != nullptr) {
                        float4 sc4 = *reinterpret_cast<const float4*>(scB + c2);
                        float4 sh4 = *reinterpret_cast<const float4*>(shB + c2);
                        v.x = fmaf(v.x, sc4.x, sh4.x);
                        v.y = fmaf(v.y, sc4.y, sh4.y);
                        v.z = fmaf(v.z, sc4.z, sh4.z);
                        v.w = fmaf(v.w, sc4.w, sh4.w);
                    }
                } else {
                    v = *reinterpret_cast<const float4*>(A + (size_t)row * K1 + gc);
                    if (scA != nullptr) {
                        float4 sc4 = *reinterpret_cast<const float4*>(scA + gc);
                        float4 sh4 = *reinterpret_cast<const float4*>(shA + gc);
                        v.x = fmaf(v.x, sc4.x, sh4.x);
                        v.y = fmaf(v.y, sc4.y, sh4.y);
                        v.z = fmaf(v.z, sc4.z, sh4.z);
                        v.w = fmaf(v.w, sc4.w, sh4.w);
                    }
                    if (Aadd != nullptr) {
                        float4 v2 = *reinterpret_cast<const float4*>(Aadd + (size_t)row * K1 + gc);
                        v.x += v2.x; v.y += v2.y; v.z += v2.z; v.w += v2.w;
                    }
                }
            }
            buf[k4 + 0][m] = v.x;
            buf[k4 + 1][m] = v.y;
            buf[k4 + 2][m] = v.z;
            buf[k4 + 3][m] = v.w;
        }
    };

    float acc[TM][4];
#pragma unroll
    for (int i = 0; i < TM; i++) { acc[i][0]=0.f; acc[i][1]=0.f; acc[i][2]=0.f; acc[i][3]=0.f; }

    loadA(0, At[0]);
    __syncthreads();

#pragma unroll
    for (int c = 0; c < NCHUNK; c++) {
        const int cur = c & 1;
        if (c + 1 < NCHUNK) loadA((c + 1) * BK, At[cur ^ 1]);

#pragma unroll 8
        for (int k = 0; k < BK; k++) {
            float4 wv = *reinterpret_cast<const float4*>(&Wt[c * BK + k][tx * 4]);
            float av[TM];
            if constexpr (TM % 4 == 0) {
#pragma unroll
                for (int ii = 0; ii < TM / 4; ii++) {
                    float4 a4 = *reinterpret_cast<const float4*>(&At[cur][k][ty * TM + ii * 4]);
                    av[ii*4+0] = a4.x; av[ii*4+1] = a4.y; av[ii*4+2] = a4.z; av[ii*4+3] = a4.w;
                }
            } else {
                float2 a2 = *reinterpret_cast<const float2*>(&At[cur][k][ty * TM]);
                av[0] = a2.x; av[1] = a2.y;
            }
#pragma unroll
            for (int i = 0; i < TM; i++) {
                acc[i][0] = fmaf(av[i], wv.x, acc[i][0]);
                acc[i][1] = fmaf(av[i], wv.y, acc[i][1]);
                acc[i][2] = fmaf(av[i], wv.z, acc[i][2]);
                acc[i][3] = fmaf(av[i], wv.w, acc[i][3]);
            }
        }
        __syncthreads();
    }

    // ---- epilogue: bias + relu + store + BN stats ----
    float4 b4 = *reinterpret_cast<const float4*>(bias + tx * 4);
    float csum[4] = {0.f, 0.f, 0.f, 0.f};
    float csq [4] = {0.f, 0.f, 0.f, 0.f};
#pragma unroll
    for (int i = 0; i < TM; i++) {
        int row = m0 + ty * TM + i;
        if (row < M) {
            float4 o;
            o.x = fmaxf(acc[i][0] + b4.x, 0.f);
            o.y = fmaxf(acc[i][1] + b4.y, 0.f);
            o.z = fmaxf(acc[i][2] + b4.z, 0.f);
            o.w = fmaxf(acc[i][3] + b4.w, 0.f);
            *reinterpret_cast<float4*>(H + (size_t)row * BN + tx * 4) = o;
            csum[0] += o.x; csum[1] += o.y; csum[2] += o.z; csum[3] += o.w;
            csq [0] += o.x * o.x; csq[1] += o.y * o.y; csq[2] += o.z * o.z; csq[3] += o.w * o.w;
        }
    }
    atomicAdd(&s_sum[tx * 4 + 0], csum[0]);
    atomicAdd(&s_sum[tx * 4 + 1], csum[1]);
    atomicAdd(&s_sum[tx * 4 + 2], csum[2]);
    atomicAdd(&s_sum[tx * 4 + 3], csum[3]);
    atomicAdd(&s_sq [tx * 4 + 0], csq[0]);
    atomicAdd(&s_sq [tx * 4 + 1], csq[1]);
    atomicAdd(&s_sq [tx * 4 + 2], csq[2]);
    atomicAdd(&s_sq [tx * 4 + 3], csq[3]);
    __syncthreads();
    for (int t = tid; t < BN; t += THREADS) {
        atomicAdd(stats + t,      s_sum[t]);
        atomicAdd(stats + 96 + t, s_sq[t]);
    }
}

// ================= BN finalize =================
__global__ void finalize_kernel(const float* __restrict__ stats,
                                const float* __restrict__ g,
                                const float* __restrict__ beta,
                                float* __restrict__ scale,
                                float* __restrict__ shift,
                                int BNc, int M)
{
    int t = threadIdx.x;
    if (t < BNc) {
        float invM = 1.0f / (float)M;
        float mu   = stats[t] * invM;
        float var  = stats[96 + t] * invM - mu * mu;
        float inv  = rsqrtf(var + 1e-5f);
        float sc   = g[t] * inv;
        scale[t] = sc;
        shift[t] = fmaf(-mu, sc, beta[t]);
    }
}

// ================= fused finalize + normalize for the [N,16] output =================
__global__ void norm16_kernel(const float* __restrict__ Hin,
                              const float* __restrict__ stats,
                              const float* __restrict__ g,
                              const float* __restrict__ beta,
                              float* __restrict__ out, int n4)
{
    int i = blockIdx.x * blockDim.x + threadIdx.x;
    if (i >= n4) return;
    int c4 = (i & 3) * 4;
    float invM = 1.0f / (float)NN;
    float4 sc, sh;
    {
        float4 su = *reinterpret_cast<const float4*>(stats + c4);
        float4 sq = *reinterpret_cast<const float4*>(stats + 96 + c4);
        float4 gg = *reinterpret_cast<const float4*>(g + c4);
        float4 bb = *reinterpret_cast<const float4*>(beta + c4);
        float mu, var;
        mu = su.x * invM; var = sq.x * invM - mu * mu; sc.x = gg.x * rsqrtf(var + 1e-5f); sh.x = fmaf(-mu, sc.x, bb.x);
        mu = su.y * invM; var = sq.y * invM - mu * mu; sc.y = gg.y * rsqrtf(var + 1e-5f); sh.y = fmaf(-mu, sc.y, bb.y);
        mu = su.z * invM; var = sq.z * invM - mu * mu; sc.z = gg.z * rsqrtf(var + 1e-5f); sh.z = fmaf(-mu, sc.z, bb.z);
        mu = su.w * invM; var = sq.w * invM - mu * mu; sc.w = gg.w * rsqrtf(var + 1e-5f); sh.w = fmaf(-mu, sc.w, bb.w);
    }
    float4 v = reinterpret_cast<const float4*>(Hin)[i];
    float4 r;
    r.x = fmaf(v.x, sc.x, sh.x);
    r.y = fmaf(v.y, sc.y, sh.y);
    r.z = fmaf(v.z, sc.z, sh.z);
    r.w = fmaf(v.w, sc.w, sh.w);
    reinterpret_cast<float4*>(out)[i] = r;
}

// ================= host =================
extern "C" void kernel_launch(void* const* d_in, const int* in_sizes, int n_in,
                              void* d_out, int out_size)
{
    const float* x   = (const float*)d_in[0];
    const float* ea  = (const float*)d_in[1];
    const int*   ei  = (const int*)  d_in[2];
    const float* lw  = (const float*)d_in[3];
    const float* lb  = (const float*)d_in[4];
    const float* w1  = (const float*)d_in[5];
    const float* b1  = (const float*)d_in[6];
    const float* g1  = (const float*)d_in[7];
    const float* be1 = (const float*)d_in[8];
    const float* w2  = (const float*)d_in[9];
    const float* b2  = (const float*)d_in[10];
    const float* g2  = (const float*)d_in[11];
    const float* be2 = (const float*)d_in[12];
    const float* w3  = (const float*)d_in[13];
    const float* b3  = (const float*)d_in[14];
    const float* g3  = (const float*)d_in[15];
    const float* be3 = (const float*)d_in[16];
    const float* w4  = (const float*)d_in[17];
    const float* b4  = (const float*)d_in[18];
    const float* g4  = (const float*)d_in[19];
    const float* be4 = (const float*)d_in[20];
    const float* w5  = (const float*)d_in[21];
    const float* b5  = (const float*)d_in[22];
    const float* g5  = (const float*)d_in[23];
    const float* be5 = (const float*)d_in[24];
    float* out = (float*)d_out;

    const int* srcp = ei;
    const int* dstp = ei + NE;

    float *agg, *h1, *h2, *h3, *h4, *h5, *stats, *scb, *shb;
    int *deg, *row_start, *pos;
    int2 *csr;
    cudaGetSymbolAddress((void**)&agg,       g_agg);
    cudaGetSymbolAddress((void**)&h1,        g_h1);
    cudaGetSymbolAddress((void**)&h2,        g_h2);
    cudaGetSymbolAddress((void**)&h3,        g_h3);
    cudaGetSymbolAddress((void**)&h4,        g_h4);
    cudaGetSymbolAddress((void**)&h5,        g_h5);
    cudaGetSymbolAddress((void**)&stats,     g_stats);
    cudaGetSymbolAddress((void**)&scb,       g_sc);
    cudaGetSymbolAddress((void**)&shb,       g_sh);
    cudaGetSymbolAddress((void**)&deg,       g_deg);
    cudaGetSymbolAddress((void**)&row_start, g_row_start);
    cudaGetSymbolAddress((void**)&pos,       g_pos);
    cudaGetSymbolAddress((void**)&csr,       g_csr);

    float* st1 = stats + 0 * 192;
    float* st2 = stats + 1 * 192;
    float* st3 = stats + 2 * 192;
    float* st4 = stats + 3 * 192;
    float* st5 = stats + 4 * 192;
    float* sc1 = scb + 0 * 96; float* sh1 = shb + 0 * 96;
    float* sc2 = scb + 1 * 96; float* sh2 = shb + 1 * 96;
    float* sc3 = scb + 2 * 96; float* sh3 = shb + 2 * 96;
    float* sc4 = scb + 3 * 96; float* sh4 = shb + 3 * 96;

    const int M = NN;
    const int eblk = (NE + 255) / 256;
    const int ablocks = (NN + 1) / 2;    // 2 nodes per 64-thread block
    const int gb128 = (M + 127) / 128;   // 391
    const int gb64  = (M + 63) / 64;

    cudaMemsetAsync(deg, 0, NN * sizeof(int), 0);
    hist_kernel<<<eblk, 256>>>(dstp, deg);
    scan_kernel<<<1, 1024>>>(deg, row_start, pos, stats);
    scatter_kernel<<<eblk, 256>>>(srcp, dstp, ea, pos, csr);

    // ---- conv1 ----
    aggregate_kernel<<<ablocks, 64>>>(x, nullptr, nullptr, lw, lb,
                                      row_start, deg, csr, agg);
    gemm_kernel<96, 24, 16, 8, 96, 3><<<gb128, 384>>>(x, nullptr, nullptr, agg,
                                                      nullptr, nullptr, nullptr, 96,
                                                      w1, b1, h1, st1, M);
    finalize_kernel<<<1, 96>>>(st1, g1, be1, sc1, sh1, 96, M);

    // ---- conv2 ----
    aggregate_kernel<<<ablocks, 64>>>(h1, sc1, sh1, lw, lb,
                                      row_start, deg, csr, agg);
    gemm_kernel<64, 16, 16, 8, 96, 3><<<gb128, 256>>>(h1, sc1, sh1, agg,
                                                      nullptr, nullptr, nullptr, 96,
                                                      w2, b2, h2, st2, M);
    finalize_kernel<<<1, 64>>>(st2, g2, be2, sc2, sh2, 64, M);

    // ---- lin1: concat(affine(h1), affine(h2)) @ w3 ----
    gemm_kernel<96, 24, 16, 8, 160, 2><<<gb128, 384>>>(h1, sc1, sh1, nullptr,
                                                       h2, sc2, sh2, 96,
                                                       w3, b3, h3, st3, M);
    finalize_kernel<<<1, 96>>>(st3, g3, be3, sc3, sh3, 96, M);

    // ---- mlp1a ----
    gemm_kernel<96, 24, 16, 8, 96, 3><<<gb128, 384>>>(h3, sc3, sh3, nullptr,
                                                      nullptr, nullptr, nullptr, 96,
                                                      w4, b4, h4, st4, M);
    finalize_kernel<<<1, 96>>>(st4, g4, be4, sc4, sh4, 96, M);

    // ---- mlp1b -> output (finalize fused into norm16) ----
    gemm_kernel<16, 4, 32, 2, 96, 2><<<gb64, 128>>>(h4, sc4, sh4, nullptr,
                                                    nullptr, nullptr, nullptr, 96,
                                                    w5, b5, h5, st5, M);
    norm16_kernel<<<(M * 4 + 255) / 256, 256>>>(h5, st5, g5, be5, out, M * 4);

    (void)in_sizes; (void)n_in; (void)out_size;
}